// round 12
// baseline (speedup 1.0000x reference)
#include <cuda_runtime.h>
#include <cuda_fp16.h>

// CustomAttention: out[b,n] = b0 * sum_m tanh(a0*x[b,n]*x[b,m]) * x[b,m]
// B=16, N=4096. Symmetric 256x256 tiling at the MUFU result roofline.
// R12: fused last-block-arrives reduction, DIAGONALS SCHEDULED FIRST.
// (R11 bug: diagonals-last made every tile's 16th feeder a final-wave
// block, serializing all 256 reductions into an exposed tail. Now the
// 16th arrival is a mid-stream off-diag block -> reductions overlap.)
// Fence-free: release atomics + __ldcg readers; launch_bounds(256,8).

#define NBATCH 16
#define NDIM   4096
#define TILE   256
#define NTILE  (NDIM / TILE)              // 16
#define NOFF   (NTILE * (NTILE - 1) / 2)  // 120
#define NPAIR  (NOFF + NTILE)             // 136
#define BT     256

__device__ __half g_scratch[NBATCH][NTILE][NDIM];   // 2 MB, exclusive-write
__device__ int    g_arrive[NBATCH][NTILE];          // zero-init; self-resetting

__device__ __forceinline__ __half2 tanh2(__half2 v) {
    unsigned u = *reinterpret_cast<unsigned*>(&v);
    unsigned r;
    asm("tanh.approx.f16x2 %0, %1;" : "=r"(r) : "r"(u));
    return *reinterpret_cast<__half2*>(&r);
}
__device__ __forceinline__ unsigned h2u(__half2 v) { return *reinterpret_cast<unsigned*>(&v); }
__device__ __forceinline__ __half2 u2h(unsigned v) { return *reinterpret_cast<__half2*>(&v); }

// Release-ordered arrival: returns previous count. No L1 flush (no MEMBAR/CCTL).
__device__ __forceinline__ int arrive_release(int* ctr) {
    int old;
    asm volatile("atom.add.release.gpu.global.s32 %0, [%1], 1;"
                 : "=r"(old) : "l"(ctr) : "memory");
    return old;
}

// Reduce output tile R: 256 threads, one row each; L2-only reads,
// two short chains to keep live-register count low.
__device__ __forceinline__ void reduce_tile(int batch, int R, float b0,
                                            float* __restrict__ out, int tid)
{
    const int n = R * TILE + tid;
    float s0 = 0.f, s1 = 0.f;
    #pragma unroll
    for (int slot = 0; slot < NTILE / 2; ++slot) {
        s0 += __half2float(__ldcg(&g_scratch[batch][2 * slot][n]));
        s1 += __half2float(__ldcg(&g_scratch[batch][2 * slot + 1][n]));
    }
    out[batch * NDIM + n] = b0 * (s0 + s1);
}

__global__ __launch_bounds__(BT, 8)      // cap regs at 32 -> 8 blocks/SM
void sym_tile_kernel(const float* __restrict__ x,
                     const float* __restrict__ a,
                     const float* __restrict__ bco,
                     float* __restrict__ out)
{
    __shared__ __half2 xhJd[4][64];            // replicated col tile, 2 KB
    __shared__ float2  colred[8][TILE / 2];    // 8 KB
    __shared__ int     s_arr[2];               // arrival ranks for tiles I, J

    const int batch = blockIdx.y;
    const int tid   = threadIdx.x;
    const int w     = tid >> 5;
    const int L     = tid & 31;

    // bid 0..15: diagonal (light, FIRST -> feeds every tile's counter early)
    // bid 16..135: off-diagonal pairs I<J
    int I, J;
    if (blockIdx.x < NTILE) {
        I = J = blockIdx.x;
    } else {
        int q = blockIdx.x - NTILE, i = 0;
        while (true) { int cnt = NTILE - 1 - i; if (q < cnt) break; q -= cnt; i++; }
        I = i; J = i + 1 + q;
    }

    const float* __restrict__ xb = x + batch * NDIM;

    // Fill replicated col tile: 4 rb x 64 entries
    {
        const int rb = tid >> 6;
        const int j  = tid & 63;
        const int pr = rb * 32 + (j & 31);
        float2 v = reinterpret_cast<const float2*>(xb + J * TILE)[pr];
        xhJd[rb][j] = __floats2half2_rn(v.x, v.y);
    }

    const float xn = xb[I * TILE + tid];
    const __half2 ch  = __float2half2_rn(a[0] * xn);
    const __half2 xi2 = __float2half2_rn(xn);
    __syncthreads();

    float row_f = 0.f;

    if (I == J) {
        #pragma unroll 1
        for (int rb = 0; rb < 4; ++rb) {
            __half2 racc = __float2half2_rn(0.f);
            #pragma unroll
            for (int k = 0; k < 32; ++k) {
                __half2 h = xhJd[rb][k];
                racc = __hfma2(tanh2(__hmul2(ch, h)), h, racc);
            }
            float2 f = __half22float2(racc);
            row_f += f.x + f.y;
        }
        g_scratch[batch][I][I * TILE + tid] = __float2half(row_f);
    } else {
        #pragma unroll 1
        for (int rb = 0; rb < 4; ++rb) {
            __half2 racc = __float2half2_rn(0.f);
            __half2 cacc = __float2half2_rn(0.f);
            #pragma unroll
            for (int k = 0; k < 32; ++k) {
                __half2 h = xhJd[rb][L + k];             // affine LDS
                __half2 t = tanh2(__hmul2(ch, h));
                racc = __hfma2(t, h, racc);              // rows of I
                unsigned v2 = h2u(__hmul2(t, xi2));      // t*x_row -> rows of J
                unsigned rv = __shfl_sync(0xffffffffu, v2, L + 32 - k);
                cacc = __hadd2(cacc, u2h(rv));
            }
            float2 f = __half22float2(racc);
            row_f += f.x + f.y;
            colred[w][rb * 32 + L] = __half22float2(cacc);
        }
        __syncthreads();

        float s = 0.f;
        #pragma unroll
        for (int w2 = 0; w2 < 8; ++w2) {
            float2 f = colred[w2][tid >> 1];
            s += (tid & 1) ? f.y : f.x;
        }
        g_scratch[batch][J][I * TILE + tid] = __float2half(row_f); // rows I, slot J
        g_scratch[batch][I][J * TILE + tid] = __float2half(s);     // rows J, slot I
    }

    // ---- last-block-arrives fused reduction (fence-free) ----
    __syncthreads();            // all scratch stores issued (write-through -> L2)
    if (tid == 0)
        s_arr[0] = arrive_release(&g_arrive[batch][I]);
    else if (tid == 32)
        s_arr[1] = (I != J) ? arrive_release(&g_arrive[batch][J]) : -1;
    __syncthreads();

    const float b0 = bco[0];
    if (s_arr[0] == NTILE - 1) {            // 16th arrival for tile I
        if (tid == 0) atomicExch(&g_arrive[batch][I], 0);   // reset for replay
        reduce_tile(batch, I, b0, out, tid);
    }
    if (s_arr[1] == NTILE - 1) {            // 16th arrival for tile J
        if (tid == 32) atomicExch(&g_arrive[batch][J], 0);
        reduce_tile(batch, J, b0, out, tid);
    }
}

extern "C" void kernel_launch(void* const* d_in, const int* in_sizes, int n_in,
                              void* d_out, int out_size)
{
    const float* x = (const float*)d_in[0];
    const float* a = (const float*)d_in[1];
    const float* b = (const float*)d_in[2];
    float* out = (float*)d_out;

    dim3 grid(NPAIR, NBATCH);               // 136 x 16 = 2176 blocks
    sym_tile_kernel<<<grid, BT>>>(x, a, b, out);
}

// round 13
// speedup vs baseline: 1.0483x; 1.0483x over previous
#include <cuda_runtime.h>
#include <cuda_fp16.h>

// CustomAttention: out[b,n] = b0 * sum_m tanh(a0*x[b,n]*x[b,m]) * x[b,m]
// B=16, N=4096. Symmetric 256x256 tiling at the MUFU result roofline.
// R13: two-kernel structure (R6, proven 41.0us) + PDL: the reduce kernel
// launches programmatically-overlapped with the main kernel's tail
// (cudaGridDependencySynchronize gates its scratch reads), hiding the
// ~4.9us launch+ramp floor that R5/R6 showed is not traffic-bound.
// In-kernel fusion (R8-R12) abandoned: epilogue cost ~6.5us regardless
// of fences/occupancy/scheduling.

#define NBATCH 16
#define NDIM   4096
#define TILE   256
#define NTILE  (NDIM / TILE)              // 16
#define NOFF   (NTILE * (NTILE - 1) / 2)  // 120
#define NPAIR  (NOFF + NTILE)             // 136
#define BT     256

__device__ __half g_scratch[NBATCH][NTILE][NDIM];   // 2 MB, exclusive-write

__device__ __forceinline__ __half2 tanh2(__half2 v) {
    unsigned u = *reinterpret_cast<unsigned*>(&v);
    unsigned r;
    asm("tanh.approx.f16x2 %0, %1;" : "=r"(r) : "r"(u));
    return *reinterpret_cast<__half2*>(&r);
}
__device__ __forceinline__ unsigned h2u(__half2 v) { return *reinterpret_cast<unsigned*>(&v); }
__device__ __forceinline__ __half2 u2h(unsigned v) { return *reinterpret_cast<__half2*>(&v); }

__global__ __launch_bounds__(BT)
void sym_tile_kernel(const float* __restrict__ x,
                     const float* __restrict__ a)
{
    __shared__ __half2 xhJd[4][64];            // replicated col tile, 2 KB
    __shared__ float2  colred[8][TILE / 2];    // 8 KB

    const int batch = blockIdx.y;
    const int tid   = threadIdx.x;
    const int w     = tid >> 5;
    const int L     = tid & 31;

    // bid 0..119: off-diagonal pairs I<J; bid 120..135: diagonal (light, last)
    int I, J;
    if (blockIdx.x < NOFF) {
        int q = blockIdx.x, i = 0;
        while (true) { int cnt = NTILE - 1 - i; if (q < cnt) break; q -= cnt; i++; }
        I = i; J = i + 1 + q;
    } else {
        I = J = blockIdx.x - NOFF;
    }

    const float* __restrict__ xb = x + batch * NDIM;

    // Fill replicated col tile: 4 rb x 64 entries
    {
        const int rb = tid >> 6;
        const int j  = tid & 63;
        const int pr = rb * 32 + (j & 31);
        float2 v = reinterpret_cast<const float2*>(xb + J * TILE)[pr];
        xhJd[rb][j] = __floats2half2_rn(v.x, v.y);
    }

    const float xn = xb[I * TILE + tid];
    const __half2 ch  = __float2half2_rn(a[0] * xn);
    const __half2 xi2 = __float2half2_rn(xn);
    __syncthreads();

    float row_f = 0.f;

    if (I == J) {
        #pragma unroll 1
        for (int rb = 0; rb < 4; ++rb) {
            __half2 racc = __float2half2_rn(0.f);
            #pragma unroll
            for (int k = 0; k < 32; ++k) {
                __half2 h = xhJd[rb][k];
                racc = __hfma2(tanh2(__hmul2(ch, h)), h, racc);
            }
            float2 f = __half22float2(racc);
            row_f += f.x + f.y;
        }
        g_scratch[batch][I][I * TILE + tid] = __float2half(row_f);
    } else {
        #pragma unroll 1
        for (int rb = 0; rb < 4; ++rb) {
            __half2 racc = __float2half2_rn(0.f);
            __half2 cacc = __float2half2_rn(0.f);
            #pragma unroll
            for (int k = 0; k < 32; ++k) {
                __half2 h = xhJd[rb][L + k];             // affine LDS
                __half2 t = tanh2(__hmul2(ch, h));
                racc = __hfma2(t, h, racc);              // rows of I
                unsigned v2 = h2u(__hmul2(t, xi2));      // t*x_row -> rows of J
                unsigned rv = __shfl_sync(0xffffffffu, v2, L + 32 - k);
                cacc = __hadd2(cacc, u2h(rv));
            }
            float2 f = __half22float2(racc);
            row_f += f.x + f.y;
            colred[w][rb * 32 + L] = __half22float2(cacc);
        }
        __syncthreads();

        float s = 0.f;
        #pragma unroll
        for (int w2 = 0; w2 < 8; ++w2) {
            float2 f = colred[w2][tid >> 1];
            s += (tid & 1) ? f.y : f.x;
        }
        g_scratch[batch][J][I * TILE + tid] = __float2half(row_f); // rows I, slot J
        g_scratch[batch][I][J * TILE + tid] = __float2half(s);     // rows J, slot I
    }

    // PDL: signal this block's scratch writes are done. The dependent
    // reduce kernel's cudaGridDependencySynchronize() releases only after
    // ALL blocks trigger (release/acquire pair -> scratch visible).
    __syncthreads();
    cudaTriggerProgrammaticLaunchCompletion();
}

// 256 blocks x 256 threads, one output per thread, 16 contiguous f16 loads.
// Launched with programmatic stream serialization: starts during the main
// kernel's tail, parks in GridDependencySynchronize until triggers arrive.
__global__ __launch_bounds__(BT)
void reduce_kernel(const float* __restrict__ b, float* __restrict__ out)
{
    const int idx   = blockIdx.x * BT + threadIdx.x;   // 0..65535
    const int batch = idx >> 12;
    const int n     = idx & (NDIM - 1);
    const float b0  = b[0];                 // independent of scratch: pre-sync

    cudaGridDependencySynchronize();        // wait for all main-kernel blocks

    float s = 0.f;
    #pragma unroll
    for (int slot = 0; slot < NTILE; ++slot)
        s += __half2float(g_scratch[batch][slot][n]);
    out[idx] = b0 * s;
}

extern "C" void kernel_launch(void* const* d_in, const int* in_sizes, int n_in,
                              void* d_out, int out_size)
{
    const float* x = (const float*)d_in[0];
    const float* a = (const float*)d_in[1];
    const float* b = (const float*)d_in[2];
    float* out = (float*)d_out;

    dim3 grid(NPAIR, NBATCH);                       // 136 x 16 = 2176 blocks
    sym_tile_kernel<<<grid, BT>>>(x, a);

    cudaLaunchConfig_t cfg = {};
    cfg.gridDim  = dim3((NBATCH * NDIM) / BT);      // 256 blocks
    cfg.blockDim = dim3(BT);
    cfg.stream   = 0;
    cudaLaunchAttribute attrs[1];
    attrs[0].id = cudaLaunchAttributeProgrammaticStreamSerialization;
    attrs[0].val.programmaticStreamSerializationAllowed = 1;
    cfg.attrs    = attrs;
    cfg.numAttrs = 1;
    cudaLaunchKernelEx(&cfg, reduce_kernel, b, out);
}